// round 5
// baseline (speedup 1.0000x reference)
#include <cuda_runtime.h>
#include <math.h>

// ---------------------------------------------------------------------------
// Scratch activations (no cudaMalloc allowed -> __device__ globals).
//   bufA: h1 [16384x2048]  -> later reused as h41|h42 (two 16384x1024 halves)
//   bufB: h2 [16384x2048]
//   bufC: h31|h32 (two 16384x1024 halves)
// ---------------------------------------------------------------------------
__device__ float g_bufA[(size_t)16384 * 2048];
__device__ float g_bufB[(size_t)16384 * 2048];
__device__ float g_bufC[(size_t)16384 * 2048];
__device__ float g_x51[(size_t)16384 * 20];
__device__ float g_x52[(size_t)16384 * 11];

// ---------------------------------------------------------------------------
// Layer 1: h1 = relu(x[16384,4] @ W1^T[4,2048] + b1)   (K=4, memory-bound)
// ---------------------------------------------------------------------------
__global__ void layer1_kernel(const float* __restrict__ x,
                              const float* __restrict__ W1,
                              const float* __restrict__ b1,
                              float* __restrict__ h1)
{
    int n = blockIdx.x * blockDim.x + threadIdx.x;   // 0..2047
    int m = blockIdx.y;                              // 0..16383
    float4 xv = reinterpret_cast<const float4*>(x)[m];
    float4 wv = reinterpret_cast<const float4*>(W1)[n];
    float s = fmaf(xv.x, wv.x, fmaf(xv.y, wv.y, fmaf(xv.z, wv.z, xv.w * wv.w))) + b1[n];
    h1[(size_t)m * 2048 + n] = fmaxf(s, 0.f);
}

// ---------------------------------------------------------------------------
// SIMT SGEMM (NT): C[M,N] = act(A[M,K] @ W[N,K]^T + bias)
// 128x128 tile, BK=8, 8x8 per-thread micro-tile, 256 threads.
// ACT: 0 = identity, 1 = relu, 2 = 4*sigmoid
// Requires: M % 128 == 0, K % 8 == 0. N may be arbitrary (bounds-checked).
// ---------------------------------------------------------------------------
template <int ACT>
__global__ __launch_bounds__(256) void sgemm_nt(
    const float* __restrict__ A, const float* __restrict__ W,
    const float* __restrict__ bias, float* __restrict__ C,
    int M, int N, int K)
{
    __shared__ float As[8][128];
    __shared__ float Ws[8][128];

    const int tid = threadIdx.x;
    const int tx = tid & 15;        // 0..15 -> n micro-tile
    const int ty = tid >> 4;        // 0..15 -> m micro-tile
    const int m0 = blockIdx.y * 128;
    const int n0 = blockIdx.x * 128;

    const int lrow = tid >> 1;          // 0..127 (tile row loaded by this thread)
    const int lk   = (tid & 1) * 4;     // 0 or 4

    const float* Ap = A + (size_t)(m0 + lrow) * K + lk;
    const int wrow = n0 + lrow;
    const float* Wp = W + (size_t)wrow * K + lk;
    const bool wok = (wrow < N);

    float acc[8][8];
#pragma unroll
    for (int i = 0; i < 8; i++)
#pragma unroll
        for (int j = 0; j < 8; j++) acc[i][j] = 0.f;

    for (int k0 = 0; k0 < K; k0 += 8) {
        float4 av = *reinterpret_cast<const float4*>(Ap + k0);
        float4 wv = wok ? *reinterpret_cast<const float4*>(Wp + k0)
                        : make_float4(0.f, 0.f, 0.f, 0.f);
        As[lk + 0][lrow] = av.x; As[lk + 1][lrow] = av.y;
        As[lk + 2][lrow] = av.z; As[lk + 3][lrow] = av.w;
        Ws[lk + 0][lrow] = wv.x; Ws[lk + 1][lrow] = wv.y;
        Ws[lk + 2][lrow] = wv.z; Ws[lk + 3][lrow] = wv.w;
        __syncthreads();

#pragma unroll
        for (int kk = 0; kk < 8; kk++) {
            float ar[8], wr[8];
            *reinterpret_cast<float4*>(ar)     = *reinterpret_cast<const float4*>(&As[kk][ty * 8]);
            *reinterpret_cast<float4*>(ar + 4) = *reinterpret_cast<const float4*>(&As[kk][ty * 8 + 4]);
            *reinterpret_cast<float4*>(wr)     = *reinterpret_cast<const float4*>(&Ws[kk][tx * 8]);
            *reinterpret_cast<float4*>(wr + 4) = *reinterpret_cast<const float4*>(&Ws[kk][tx * 8 + 4]);
#pragma unroll
            for (int i = 0; i < 8; i++)
#pragma unroll
                for (int j = 0; j < 8; j++)
                    acc[i][j] = fmaf(ar[i], wr[j], acc[i][j]);
        }
        __syncthreads();
    }

    const bool full_n = (n0 + 128) <= N;
#pragma unroll
    for (int i = 0; i < 8; i++) {
        const int row = m0 + ty * 8 + i;
        if (full_n) {
            const int col = n0 + tx * 8;
            float c[8];
#pragma unroll
            for (int j = 0; j < 8; j++) {
                float v = acc[i][j] + bias[col + j];
                if (ACT == 1) v = fmaxf(v, 0.f);
                if (ACT == 2) v = 4.f / (1.f + expf(-v));
                c[j] = v;
            }
            float4* dst = reinterpret_cast<float4*>(&C[(size_t)row * N + col]);
            dst[0] = make_float4(c[0], c[1], c[2], c[3]);
            dst[1] = make_float4(c[4], c[5], c[6], c[7]);
        } else {
#pragma unroll
            for (int j = 0; j < 8; j++) {
                const int col = n0 + tx * 8 + j;
                if (col < N) {
                    float v = acc[i][j] + bias[col];
                    if (ACT == 1) v = fmaxf(v, 0.f);
                    if (ACT == 2) v = 4.f / (1.f + expf(-v));
                    C[(size_t)row * N + col] = v;
                }
            }
        }
    }
}

// ---------------------------------------------------------------------------
// Fused CBF-QP epilogue: per batch row, compute barrier dynamics, 10-head
// QP projection, softmax(wt)-weighted mix, then label de-normalization.
// ---------------------------------------------------------------------------
__global__ void final_kernel(const float* __restrict__ x,
                             const float* __restrict__ mean,
                             const float* __restrict__ stdv,
                             const float* __restrict__ mean_label,
                             const float* __restrict__ std_label,
                             const float* __restrict__ x51,
                             const float* __restrict__ x52,
                             const float* __restrict__ wt,
                             float* __restrict__ out)
{
    int b = blockIdx.x * blockDim.x + threadIdx.x;
    if (b >= 16384) return;

    float4 xv = reinterpret_cast<const float4*>(x)[b];
    float th1 = xv.x * stdv[0] + mean[0];
    float w1v = xv.y * stdv[1] + mean[1];
    float th2 = xv.z * stdv[2] + mean[2];
    float w2v = xv.w * stdv[3] + mean[3];

    float s1, c1, s2, c2;
    sincosf(th1, &s1, &c1);
    sincosf(th2, &s2, &c2);

    const float Lc = 3.0f;                     // L1 = L2 = 3
    float px = Lc * c1 + Lc * c2 - 0.0f;       // OBS_X = 0
    float py = Lc * s1 + Lc * s2 - 7.0f;       // OBS_Y = 7
    float vx = -Lc * s1 * w1v - Lc * s2 * w2v;
    float vy =  Lc * c1 * w1v + Lc * c2 * w2v;
    float barrier = px * px + py * py - 16.0f; // R^2 = 16
    float b_dot = 2.0f * (px * vx + py * vy);
    float Lf2b = 2.0f * vx * vx + 2.0f * vy * vy
               + 2.0f * px * (-Lc * c1 * w1v * w1v - Lc * c2 * w2v * w2v)
               + 2.0f * py * (-Lc * s1 * w1v * w1v - Lc * s2 * w2v * w2v);
    float g1 = 2.0f * px * (-Lc * s1) + 2.0f * py * (Lc * c1);
    float g2 = 2.0f * px * (-Lc * s2) + 2.0f * py * (Lc * c2);
    float Gx = -g1, Gy = -g2;
    float Gdot = g1 * g1 + g2 * g2;

    // softmax over wt (10 heads)
    float wmax = wt[0];
#pragma unroll
    for (int h = 1; h < 10; h++) wmax = fmaxf(wmax, wt[h]);
    float wv[10];
    float wsum = 0.f;
#pragma unroll
    for (int h = 0; h < 10; h++) { wv[h] = expf(wt[h] - wmax); wsum += wv[h]; }
    float winv = 1.f / wsum;

    float alpha = x52[(size_t)b * 11 + 0];
    float ax = 0.f, ay = 0.f;
#pragma unroll
    for (int h = 0; h < 10; h++) {
        float beta = x52[(size_t)b * 11 + 1 + h];
        float refx = x51[(size_t)b * 20 + 2 * h];
        float refy = x51[(size_t)b * 20 + 2 * h + 1];
        float ux = -refx, uy = -refy;
        float hv = Lf2b + (alpha + beta) * b_dot + alpha * beta * barrier;
        float viol = ux * Gx + uy * Gy - hv;
        float lam = fmaxf(viol / Gdot, 0.f);
        float solx = ux - lam * Gx;
        float soly = uy - lam * Gy;
        float wh = wv[h] * winv;
        ax = fmaf(wh, solx, ax);
        ay = fmaf(wh, soly, ay);
    }
    out[(size_t)b * 2 + 0] = (ax - mean_label[0]) / std_label[0];
    out[(size_t)b * 2 + 1] = (ay - mean_label[1]) / std_label[1];
}

// ---------------------------------------------------------------------------
// kernel_launch
// Input order (metadata): 0:x 1:sgn 2:mean 3:std 4:mean_label 5:std_label
//   6:W1 7:b1 8:W2 9:b2 10:W31 11:b31 12:W32 13:b32 14:W41 15:b41
//   16:W42 17:b42 18:W51 19:b51 20:W52 21:b52 22:wt
// ---------------------------------------------------------------------------
extern "C" void kernel_launch(void* const* d_in, const int* in_sizes, int n_in,
                              void* d_out, int out_size)
{
    (void)in_sizes; (void)n_in; (void)out_size;

    const float* x          = (const float*)d_in[0];
    const float* mean       = (const float*)d_in[2];
    const float* stdv       = (const float*)d_in[3];
    const float* mean_label = (const float*)d_in[4];
    const float* std_label  = (const float*)d_in[5];
    const float* W1  = (const float*)d_in[6];   const float* b1  = (const float*)d_in[7];
    const float* W2  = (const float*)d_in[8];   const float* b2  = (const float*)d_in[9];
    const float* W31 = (const float*)d_in[10];  const float* b31 = (const float*)d_in[11];
    const float* W32 = (const float*)d_in[12];  const float* b32 = (const float*)d_in[13];
    const float* W41 = (const float*)d_in[14];  const float* b41 = (const float*)d_in[15];
    const float* W42 = (const float*)d_in[16];  const float* b42 = (const float*)d_in[17];
    const float* W51 = (const float*)d_in[18];  const float* b51 = (const float*)d_in[19];
    const float* W52 = (const float*)d_in[20];  const float* b52 = (const float*)d_in[21];
    const float* wt  = (const float*)d_in[22];
    float* out = (float*)d_out;

    // Resolve scratch symbol addresses once (non-stream API; capture-safe).
    static float *bufA = nullptr, *bufB = nullptr, *bufC = nullptr,
                 *x51p = nullptr, *x52p = nullptr;
    if (!bufA) {
        cudaGetSymbolAddress((void**)&bufA, g_bufA);
        cudaGetSymbolAddress((void**)&bufB, g_bufB);
        cudaGetSymbolAddress((void**)&bufC, g_bufC);
        cudaGetSymbolAddress((void**)&x51p, g_x51);
        cudaGetSymbolAddress((void**)&x52p, g_x52);
    }

    float* h1  = bufA;
    float* h2  = bufB;
    float* h31 = bufC;
    float* h32 = bufC + (size_t)16384 * 1024;
    float* h41 = bufA;                              // bufA free after GEMM2
    float* h42 = bufA + (size_t)16384 * 1024;

    dim3 t256(256);

    // Layer 1: [16384,4] -> [16384,2048]
    layer1_kernel<<<dim3(2048 / 256, 16384), t256>>>(x, W1, b1, h1);

    // Layer 2: 16384 x 2048 x 2048 (relu)
    sgemm_nt<1><<<dim3(16, 128), t256>>>(h1, W2, b2, h2, 16384, 2048, 2048);

    // Layer 3a/3b: 16384 x 1024 x 2048 (relu)
    sgemm_nt<1><<<dim3(8, 128), t256>>>(h2, W31, b31, h31, 16384, 1024, 2048);
    sgemm_nt<1><<<dim3(8, 128), t256>>>(h2, W32, b32, h32, 16384, 1024, 2048);

    // Layer 4a/4b: 16384 x 1024 x 1024 (relu)
    sgemm_nt<1><<<dim3(8, 128), t256>>>(h31, W41, b41, h41, 16384, 1024, 1024);
    sgemm_nt<1><<<dim3(8, 128), t256>>>(h32, W42, b42, h42, 16384, 1024, 1024);

    // Heads: 16384 x 20 x 1024 (identity), 16384 x 11 x 1024 (4*sigmoid)
    sgemm_nt<0><<<dim3(1, 128), t256>>>(h41, W51, b51, x51p, 16384, 20, 1024);
    sgemm_nt<2><<<dim3(1, 128), t256>>>(h42, W52, b52, x52p, 16384, 11, 1024);

    // Fused CBF-QP epilogue + denorm
    final_kernel<<<16384 / 256, 256>>>(x, mean, stdv, mean_label, std_label,
                                       x51p, x52p, wt, out);
}

// round 6
// speedup vs baseline: 1.6065x; 1.6065x over previous
#include <cuda_runtime.h>
#include <math.h>

// ---------------------------------------------------------------------------
// Scratch activations (no cudaMalloc allowed -> __device__ globals).
//   bufA: h1 [16384x2048]  -> later reused as h41|h42 (two 16384x1024 halves)
//   bufB: h2 [16384x2048]
//   bufC: h31|h32 (two 16384x1024 halves)
// ---------------------------------------------------------------------------
__device__ float g_bufA[(size_t)16384 * 2048];
__device__ float g_bufB[(size_t)16384 * 2048];
__device__ float g_bufC[(size_t)16384 * 2048];
__device__ float g_x51[(size_t)16384 * 20];
__device__ float g_x52[(size_t)16384 * 11];

// ---------------------------------------------------------------------------
// Layer 1: h1 = relu(x[16384,4] @ W1^T[4,2048] + b1)   (K=4, memory-bound)
// ---------------------------------------------------------------------------
__global__ void layer1_kernel(const float* __restrict__ x,
                              const float* __restrict__ W1,
                              const float* __restrict__ b1,
                              float* __restrict__ h1)
{
    int n = blockIdx.x * blockDim.x + threadIdx.x;   // 0..2047
    int m = blockIdx.y;                              // 0..16383
    float4 xv = reinterpret_cast<const float4*>(x)[m];
    float4 wv = reinterpret_cast<const float4*>(W1)[n];
    float s = fmaf(xv.x, wv.x, fmaf(xv.y, wv.y, fmaf(xv.z, wv.z, xv.w * wv.w))) + b1[n];
    h1[(size_t)m * 2048 + n] = fmaxf(s, 0.f);
}

// ---------------------------------------------------------------------------
// SIMT SGEMM (NT): C[M,N] = act(A[M,K] @ W[N,K]^T + bias)
// 128x128 tile, BK=8, 8x8 per-thread micro-tile, 256 threads.
// ACT: 0 = identity, 1 = relu, 2 = 4*sigmoid
// Requires: M % 128 == 0, K % 8 == 0. N may be arbitrary (bounds-checked).
// ---------------------------------------------------------------------------
template <int ACT>
__global__ __launch_bounds__(256) void sgemm_nt(
    const float* __restrict__ A, const float* __restrict__ W,
    const float* __restrict__ bias, float* __restrict__ C,
    int M, int N, int K)
{
    __shared__ float As[8][128];
    __shared__ float Ws[8][128];

    const int tid = threadIdx.x;
    const int tx = tid & 15;        // 0..15 -> n micro-tile
    const int ty = tid >> 4;        // 0..15 -> m micro-tile
    const int m0 = blockIdx.y * 128;
    const int n0 = blockIdx.x * 128;

    const int lrow = tid >> 1;          // 0..127 (tile row loaded by this thread)
    const int lk   = (tid & 1) * 4;     // 0 or 4

    const float* Ap = A + (size_t)(m0 + lrow) * K + lk;
    const int wrow = n0 + lrow;
    const float* Wp = W + (size_t)wrow * K + lk;
    const bool wok = (wrow < N);

    float acc[8][8];
#pragma unroll
    for (int i = 0; i < 8; i++)
#pragma unroll
        for (int j = 0; j < 8; j++) acc[i][j] = 0.f;

    for (int k0 = 0; k0 < K; k0 += 8) {
        float4 av = *reinterpret_cast<const float4*>(Ap + k0);
        float4 wv = wok ? *reinterpret_cast<const float4*>(Wp + k0)
                        : make_float4(0.f, 0.f, 0.f, 0.f);
        As[lk + 0][lrow] = av.x; As[lk + 1][lrow] = av.y;
        As[lk + 2][lrow] = av.z; As[lk + 3][lrow] = av.w;
        Ws[lk + 0][lrow] = wv.x; Ws[lk + 1][lrow] = wv.y;
        Ws[lk + 2][lrow] = wv.z; Ws[lk + 3][lrow] = wv.w;
        __syncthreads();

#pragma unroll
        for (int kk = 0; kk < 8; kk++) {
            float ar[8], wr[8];
            *reinterpret_cast<float4*>(ar)     = *reinterpret_cast<const float4*>(&As[kk][ty * 8]);
            *reinterpret_cast<float4*>(ar + 4) = *reinterpret_cast<const float4*>(&As[kk][ty * 8 + 4]);
            *reinterpret_cast<float4*>(wr)     = *reinterpret_cast<const float4*>(&Ws[kk][tx * 8]);
            *reinterpret_cast<float4*>(wr + 4) = *reinterpret_cast<const float4*>(&Ws[kk][tx * 8 + 4]);
#pragma unroll
            for (int i = 0; i < 8; i++)
#pragma unroll
                for (int j = 0; j < 8; j++)
                    acc[i][j] = fmaf(ar[i], wr[j], acc[i][j]);
        }
        __syncthreads();
    }

    const bool full_n = (n0 + 128) <= N;
#pragma unroll
    for (int i = 0; i < 8; i++) {
        const int row = m0 + ty * 8 + i;
        if (full_n) {
            const int col = n0 + tx * 8;
            float c[8];
#pragma unroll
            for (int j = 0; j < 8; j++) {
                float v = acc[i][j] + bias[col + j];
                if (ACT == 1) v = fmaxf(v, 0.f);
                if (ACT == 2) v = 4.f / (1.f + expf(-v));
                c[j] = v;
            }
            float4* dst = reinterpret_cast<float4*>(&C[(size_t)row * N + col]);
            dst[0] = make_float4(c[0], c[1], c[2], c[3]);
            dst[1] = make_float4(c[4], c[5], c[6], c[7]);
        } else {
#pragma unroll
            for (int j = 0; j < 8; j++) {
                const int col = n0 + tx * 8 + j;
                if (col < N) {
                    float v = acc[i][j] + bias[col];
                    if (ACT == 1) v = fmaxf(v, 0.f);
                    if (ACT == 2) v = 4.f / (1.f + expf(-v));
                    C[(size_t)row * N + col] = v;
                }
            }
        }
    }
}

// ---------------------------------------------------------------------------
// Fused CBF-QP epilogue: per batch row, compute barrier dynamics, 10-head
// QP projection, softmax(wt)-weighted mix, then label de-normalization.
// ---------------------------------------------------------------------------
__global__ void final_kernel(const float* __restrict__ x,
                             const float* __restrict__ mean,
                             const float* __restrict__ stdv,
                             const float* __restrict__ mean_label,
                             const float* __restrict__ std_label,
                             const float* __restrict__ x51,
                             const float* __restrict__ x52,
                             const float* __restrict__ wt,
                             float* __restrict__ out)
{
    int b = blockIdx.x * blockDim.x + threadIdx.x;
    if (b >= 16384) return;

    float4 xv = reinterpret_cast<const float4*>(x)[b];
    float th1 = xv.x * stdv[0] + mean[0];
    float w1v = xv.y * stdv[1] + mean[1];
    float th2 = xv.z * stdv[2] + mean[2];
    float w2v = xv.w * stdv[3] + mean[3];

    float s1, c1, s2, c2;
    sincosf(th1, &s1, &c1);
    sincosf(th2, &s2, &c2);

    const float Lc = 3.0f;                     // L1 = L2 = 3
    float px = Lc * c1 + Lc * c2 - 0.0f;       // OBS_X = 0
    float py = Lc * s1 + Lc * s2 - 7.0f;       // OBS_Y = 7
    float vx = -Lc * s1 * w1v - Lc * s2 * w2v;
    float vy =  Lc * c1 * w1v + Lc * c2 * w2v;
    float barrier = px * px + py * py - 16.0f; // R^2 = 16
    float b_dot = 2.0f * (px * vx + py * vy);
    float Lf2b = 2.0f * vx * vx + 2.0f * vy * vy
               + 2.0f * px * (-Lc * c1 * w1v * w1v - Lc * c2 * w2v * w2v)
               + 2.0f * py * (-Lc * s1 * w1v * w1v - Lc * s2 * w2v * w2v);
    float g1 = 2.0f * px * (-Lc * s1) + 2.0f * py * (Lc * c1);
    float g2 = 2.0f * px * (-Lc * s2) + 2.0f * py * (Lc * c2);
    float Gx = -g1, Gy = -g2;
    float Gdot = g1 * g1 + g2 * g2;

    // softmax over wt (10 heads)
    float wmax = wt[0];
#pragma unroll
    for (int h = 1; h < 10; h++) wmax = fmaxf(wmax, wt[h]);
    float wv[10];
    float wsum = 0.f;
#pragma unroll
    for (int h = 0; h < 10; h++) { wv[h] = expf(wt[h] - wmax); wsum += wv[h]; }
    float winv = 1.f / wsum;

    float alpha = x52[(size_t)b * 11 + 0];
    float ax = 0.f, ay = 0.f;
#pragma unroll
    for (int h = 0; h < 10; h++) {
        float beta = x52[(size_t)b * 11 + 1 + h];
        float refx = x51[(size_t)b * 20 + 2 * h];
        float refy = x51[(size_t)b * 20 + 2 * h + 1];
        float ux = -refx, uy = -refy;
        float hv = Lf2b + (alpha + beta) * b_dot + alpha * beta * barrier;
        float viol = ux * Gx + uy * Gy - hv;
        float lam = fmaxf(viol / Gdot, 0.f);
        float solx = ux - lam * Gx;
        float soly = uy - lam * Gy;
        float wh = wv[h] * winv;
        ax = fmaf(wh, solx, ax);
        ay = fmaf(wh, soly, ay);
    }
    out[(size_t)b * 2 + 0] = (ax - mean_label[0]) / std_label[0];
    out[(size_t)b * 2 + 1] = (ay - mean_label[1]) / std_label[1];
}

// ---------------------------------------------------------------------------
// kernel_launch
// Input order (metadata): 0:x 1:sgn 2:mean 3:std 4:mean_label 5:std_label
//   6:W1 7:b1 8:W2 9:b2 10:W31 11:b31 12:W32 13:b32 14:W41 15:b41
//   16:W42 17:b42 18:W51 19:b51 20:W52 21:b52 22:wt
// ---------------------------------------------------------------------------
extern "C" void kernel_launch(void* const* d_in, const int* in_sizes, int n_in,
                              void* d_out, int out_size)
{
    (void)in_sizes; (void)n_in; (void)out_size;

    const float* x          = (const float*)d_in[0];
    const float* mean       = (const float*)d_in[2];
    const float* stdv       = (const float*)d_in[3];
    const float* mean_label = (const float*)d_in[4];
    const float* std_label  = (const float*)d_in[5];
    const float* W1  = (const float*)d_in[6];   const float* b1  = (const float*)d_in[7];
    const float* W2  = (const float*)d_in[8];   const float* b2  = (const float*)d_in[9];
    const float* W31 = (const float*)d_in[10];  const float* b31 = (const float*)d_in[11];
    const float* W32 = (const float*)d_in[12];  const float* b32 = (const float*)d_in[13];
    const float* W41 = (const float*)d_in[14];  const float* b41 = (const float*)d_in[15];
    const float* W42 = (const float*)d_in[16];  const float* b42 = (const float*)d_in[17];
    const float* W51 = (const float*)d_in[18];  const float* b51 = (const float*)d_in[19];
    const float* W52 = (const float*)d_in[20];  const float* b52 = (const float*)d_in[21];
    const float* wt  = (const float*)d_in[22];
    float* out = (float*)d_out;

    // Resolve scratch symbol addresses once (non-stream API; capture-safe).
    static float *bufA = nullptr, *bufB = nullptr, *bufC = nullptr,
                 *x51p = nullptr, *x52p = nullptr;
    if (!bufA) {
        cudaGetSymbolAddress((void**)&bufA, g_bufA);
        cudaGetSymbolAddress((void**)&bufB, g_bufB);
        cudaGetSymbolAddress((void**)&bufC, g_bufC);
        cudaGetSymbolAddress((void**)&x51p, g_x51);
        cudaGetSymbolAddress((void**)&x52p, g_x52);
    }

    float* h1  = bufA;
    float* h2  = bufB;
    float* h31 = bufC;
    float* h32 = bufC + (size_t)16384 * 1024;
    float* h41 = bufA;                              // bufA free after GEMM2
    float* h42 = bufA + (size_t)16384 * 1024;

    dim3 t256(256);

    // Layer 1: [16384,4] -> [16384,2048]
    layer1_kernel<<<dim3(2048 / 256, 16384), t256>>>(x, W1, b1, h1);

    // Layer 2: 16384 x 2048 x 2048 (relu)
    sgemm_nt<1><<<dim3(16, 128), t256>>>(h1, W2, b2, h2, 16384, 2048, 2048);

    // Layer 3a/3b: 16384 x 1024 x 2048 (relu)
    sgemm_nt<1><<<dim3(8, 128), t256>>>(h2, W31, b31, h31, 16384, 1024, 2048);
    sgemm_nt<1><<<dim3(8, 128), t256>>>(h2, W32, b32, h32, 16384, 1024, 2048);

    // Layer 4a/4b: 16384 x 1024 x 1024 (relu)
    sgemm_nt<1><<<dim3(8, 128), t256>>>(h31, W41, b41, h41, 16384, 1024, 1024);
    sgemm_nt<1><<<dim3(8, 128), t256>>>(h32, W42, b42, h42, 16384, 1024, 1024);

    // Heads: 16384 x 20 x 1024 (identity), 16384 x 11 x 1024 (4*sigmoid)
    sgemm_nt<0><<<dim3(1, 128), t256>>>(h41, W51, b51, x51p, 16384, 20, 1024);
    sgemm_nt<2><<<dim3(1, 128), t256>>>(h42, W52, b52, x52p, 16384, 11, 1024);

    // Fused CBF-QP epilogue + denorm
    final_kernel<<<16384 / 256, 256>>>(x, mean, stdv, mean_label, std_label,
                                       x51p, x52p, wt, out);
}

// round 12
// speedup vs baseline: 4.8680x; 3.0302x over previous
#include <cuda_runtime.h>
#include <cuda_bf16.h>
#include <math.h>
#include <stdint.h>

#define BATCH 16384

// Scratch arenas (__device__ globals; bf16 planes share fp32-sized buffers)
__device__ float g_bufA[(size_t)BATCH * 2048];
__device__ float g_bufB[(size_t)BATCH * 2048];
__device__ float g_bufC[(size_t)BATCH * 2048];
__device__ float g_x51[(size_t)BATCH * 20];
__device__ float g_x52[(size_t)BATCH * 11];
__device__ __nv_bfloat16 g_wsplit[20971520];   // split W2,W31,W32,W41,W42 hi+lo

// ---------------- helpers ----------------
__device__ __forceinline__ uint32_t smem_u32(const void* p) {
    uint32_t a;
    asm("{ .reg .u64 t; cvta.to.shared.u64 t, %1; cvt.u32.u64 %0, t; }" : "=r"(a) : "l"(p));
    return a;
}
__device__ __forceinline__ void split_bf16(float v, unsigned short& h, unsigned short& l) {
    __nv_bfloat16 hb = __float2bfloat16(v);
    __nv_bfloat16 lb = __float2bfloat16(v - __bfloat162float(hb));
    h = __bfloat16_as_ushort(hb);
    l = __bfloat16_as_ushort(lb);
}

#define CP_ASYNC16(smem_addr, gptr) \
    asm volatile("cp.async.cg.shared.global [%0], [%1], 16;" :: "r"(smem_addr), "l"(gptr))
#define CP_COMMIT()  asm volatile("cp.async.commit_group;" ::: "memory")
#define CP_WAIT1()   asm volatile("cp.async.wait_group 1;" ::: "memory")

#define LDSM4(r, a) \
    asm volatile("ldmatrix.sync.aligned.m8n8.x4.shared.b16 {%0,%1,%2,%3}, [%4];" \
        : "=r"((r)[0]), "=r"((r)[1]), "=r"((r)[2]), "=r"((r)[3]) : "r"(a))
#define LDSM2(r, a) \
    asm volatile("ldmatrix.sync.aligned.m8n8.x2.shared.b16 {%0,%1}, [%2];" \
        : "=r"((r)[0]), "=r"((r)[1]) : "r"(a))

#define MMA16816(d, a, b) \
    asm volatile("mma.sync.aligned.m16n8k16.row.col.f32.bf16.bf16.f32 " \
        "{%0,%1,%2,%3}, {%4,%5,%6,%7}, {%8,%9}, {%0,%1,%2,%3};" \
        : "+f"((d)[0]), "+f"((d)[1]), "+f"((d)[2]), "+f"((d)[3]) \
        : "r"((a)[0]), "r"((a)[1]), "r"((a)[2]), "r"((a)[3]), \
          "r"((b)[0]), "r"((b)[1]))

// ---------------- weight split: fp32 -> hi/lo bf16 planes ----------------
__global__ void wsplit_kernel(const float* __restrict__ W,
                              __nv_bfloat16* __restrict__ hi,
                              __nv_bfloat16* __restrict__ lo, int n4)
{
    int i = blockIdx.x * blockDim.x + threadIdx.x;
    if (i >= n4) return;
    float4 w = reinterpret_cast<const float4*>(W)[i];
    unsigned short h0, l0, h1, l1, h2, l2, h3, l3;
    split_bf16(w.x, h0, l0); split_bf16(w.y, h1, l1);
    split_bf16(w.z, h2, l2); split_bf16(w.w, h3, l3);
    uint2 hv, lv;
    hv.x = (uint32_t)h0 | ((uint32_t)h1 << 16);
    hv.y = (uint32_t)h2 | ((uint32_t)h3 << 16);
    lv.x = (uint32_t)l0 | ((uint32_t)l1 << 16);
    lv.y = (uint32_t)l2 | ((uint32_t)l3 << 16);
    reinterpret_cast<uint2*>(hi)[i] = hv;
    reinterpret_cast<uint2*>(lo)[i] = lv;
}

// ---------------- layer 1 (K=4) -> split planes ----------------
__global__ void layer1_kernel(const float* __restrict__ x,
                              const float* __restrict__ W1,
                              const float* __restrict__ b1,
                              __nv_bfloat16* __restrict__ hi,
                              __nv_bfloat16* __restrict__ lo)
{
    int n = blockIdx.x * blockDim.x + threadIdx.x;
    int m = blockIdx.y;
    float4 xv = reinterpret_cast<const float4*>(x)[m];
    float4 wv = reinterpret_cast<const float4*>(W1)[n];
    float s = fmaf(xv.x, wv.x, fmaf(xv.y, wv.y, fmaf(xv.z, wv.z, xv.w * wv.w))) + b1[n];
    s = fmaxf(s, 0.f);
    unsigned short h, l;
    split_bf16(s, h, l);
    size_t idx = (size_t)m * 2048 + n;
    hi[idx] = __ushort_as_bfloat16(h);
    lo[idx] = __ushort_as_bfloat16(l);
}

// ---------------------------------------------------------------------------
// HMMA split-bf16 GEMM:  C = relu(A[M,K] @ W[N,K]^T + bias)
//   D = Ahi*Whi + Ahi*Wlo + Alo*Whi   (fp32 accum; lo*lo dropped ~1e-5 rel)
// CTA 128x128, BK=64, cp.async double buffer, 8 warps (2M x 4N, 64x32 each).
// smem stage: Ahi 16K | Alo 16K | Whi 16K | Wlo 16K = 64K; 2 stages = 128K.
// ---------------------------------------------------------------------------
#define HG_SMEM (2 * 65536)

__global__ __launch_bounds__(256, 1)
void hgemm_split(const __nv_bfloat16* __restrict__ Ahi,
                 const __nv_bfloat16* __restrict__ Alo,
                 const __nv_bfloat16* __restrict__ Whi,
                 const __nv_bfloat16* __restrict__ Wlo,
                 const float* __restrict__ bias,
                 __nv_bfloat16* __restrict__ Chi,
                 __nv_bfloat16* __restrict__ Clo,
                 int N, int K)
{
    extern __shared__ char smem[];
    const uint32_t sbase = smem_u32(smem);
    const int tid  = threadIdx.x;
    const int wid  = tid >> 5;
    const int lane = tid & 31;
    const int warpM = wid & 1;        // 2 warps in M
    const int warpN = wid >> 1;       // 4 warps in N
    const int m0 = blockIdx.y * 128;
    const int n0 = blockIdx.x * 128;

    // ---- cp.async source/dest offsets (4 chunks of 16B per thread per plane)
    const char* gAhi[4]; const char* gAlo[4]; const char* gWhi[4]; const char* gWlo[4];
    uint32_t soff[4];
#pragma unroll
    for (int j = 0; j < 4; ++j) {
        int ci = tid + (j << 8);             // 0..1023
        int row = ci >> 3, ch = ci & 7;
        size_t ga = ((size_t)(m0 + row) * K + (ch << 3)) * 2;
        size_t gw = ((size_t)(n0 + row) * K + (ch << 3)) * 2;
        gAhi[j] = (const char*)Ahi + ga;
        gAlo[j] = (const char*)Alo + ga;
        gWhi[j] = (const char*)Whi + gw;
        gWlo[j] = (const char*)Wlo + gw;
        soff[j] = (uint32_t)(row * 128 + ((ch ^ (row & 7)) << 4));
    }

    // ---- ldmatrix per-lane address pieces
    const int laneA = lane & 15;
    const uint32_t aRow = (uint32_t)(warpM * 64 + laneA) * 128;
    const uint32_t aRm  = (uint32_t)(laneA & 7);
    const uint32_t aHalf = (uint32_t)(lane >> 4);          // 0/1
    const int laneB = lane & 7;
    const uint32_t bRow = (uint32_t)(warpN * 32 + laneB) * 128;
    const uint32_t bRm  = (uint32_t)laneB;
    const uint32_t bHalf = (uint32_t)((lane >> 3) & 1);    // 0/1

    float acc[4][4][4];
#pragma unroll
    for (int mt = 0; mt < 4; ++mt)
#pragma unroll
        for (int nt = 0; nt < 4; ++nt)
#pragma unroll
            for (int r = 0; r < 4; ++r) acc[mt][nt][r] = 0.f;

    const int nK = K >> 6;

    // prefetch stage 0
    {
        uint32_t st = sbase;
#pragma unroll
        for (int j = 0; j < 4; ++j) {
            CP_ASYNC16(st + soff[j],         gAhi[j]);
            CP_ASYNC16(st + 16384 + soff[j], gAlo[j]);
            CP_ASYNC16(st + 32768 + soff[j], gWhi[j]);
            CP_ASYNC16(st + 49152 + soff[j], gWlo[j]);
        }
    }
    CP_COMMIT();

    for (int kb = 0; kb < nK; ++kb) {
        // prefetch next stage
        if (kb + 1 < nK) {
            uint32_t st = sbase + ((kb + 1) & 1) * 65536;
            const uint32_t gadd = (uint32_t)(kb + 1) * 128;
#pragma unroll
            for (int j = 0; j < 4; ++j) {
                CP_ASYNC16(st + soff[j],         gAhi[j] + gadd);
                CP_ASYNC16(st + 16384 + soff[j], gAlo[j] + gadd);
                CP_ASYNC16(st + 32768 + soff[j], gWhi[j] + gadd);
                CP_ASYNC16(st + 49152 + soff[j], gWlo[j] + gadd);
            }
        }
        CP_COMMIT();
        CP_WAIT1();
        __syncthreads();

        const uint32_t st = sbase + (kb & 1) * 65536;
#pragma unroll
        for (int ks = 0; ks < 4; ++ks) {
            const uint32_t aCh = (uint32_t)(ks * 2) + aHalf;
            const uint32_t bCh = (uint32_t)(ks * 2) + bHalf;
            uint32_t ahi[4][4], alo[4][4], bhi[4][2], blo[4][2];
#pragma unroll
            for (int mt = 0; mt < 4; ++mt) {
                uint32_t ad = st + aRow + (uint32_t)(mt * 2048) + ((aCh ^ aRm) << 4);
                LDSM4(ahi[mt], ad);
            }
#pragma unroll
            for (int nt = 0; nt < 4; ++nt) {
                uint32_t bd = st + 32768 + bRow + (uint32_t)(nt * 1024) + ((bCh ^ bRm) << 4);
                LDSM2(bhi[nt], bd);
                LDSM2(blo[nt], bd + 16384);
            }
#pragma unroll
            for (int mt = 0; mt < 4; ++mt)
#pragma unroll
                for (int nt = 0; nt < 4; ++nt)
                    MMA16816(acc[mt][nt], ahi[mt], bhi[nt]);
#pragma unroll
            for (int mt = 0; mt < 4; ++mt)
#pragma unroll
                for (int nt = 0; nt < 4; ++nt)
                    MMA16816(acc[mt][nt], ahi[mt], blo[nt]);
#pragma unroll
            for (int mt = 0; mt < 4; ++mt) {
                uint32_t ad = st + 16384 + aRow + (uint32_t)(mt * 2048) + ((aCh ^ aRm) << 4);
                LDSM4(alo[mt], ad);
            }
#pragma unroll
            for (int mt = 0; mt < 4; ++mt)
#pragma unroll
                for (int nt = 0; nt < 4; ++nt)
                    MMA16816(acc[mt][nt], alo[mt], bhi[nt]);
        }
        __syncthreads();   // all warps done reading before next prefetch overwrites
    }

    // ---- epilogue: bias + relu + split-store to hi/lo planes
    const int g = lane >> 2, t = lane & 3;
#pragma unroll
    for (int mt = 0; mt < 4; ++mt) {
        const int r0 = m0 + warpM * 64 + mt * 16 + g;
        const int r1 = r0 + 8;
#pragma unroll
        for (int nt = 0; nt < 4; ++nt) {
            const int col = n0 + warpN * 32 + nt * 8 + 2 * t;
            float2 bs = *reinterpret_cast<const float2*>(&bias[col]);
            float v00 = fmaxf(acc[mt][nt][0] + bs.x, 0.f);
            float v01 = fmaxf(acc[mt][nt][1] + bs.y, 0.f);
            float v10 = fmaxf(acc[mt][nt][2] + bs.x, 0.f);
            float v11 = fmaxf(acc[mt][nt][3] + bs.y, 0.f);
            unsigned short h0, l0, h1, l1;
            split_bf16(v00, h0, l0); split_bf16(v01, h1, l1);
            uint32_t hp = (uint32_t)h0 | ((uint32_t)h1 << 16);
            uint32_t lp = (uint32_t)l0 | ((uint32_t)l1 << 16);
            *reinterpret_cast<uint32_t*>(Chi + (size_t)r0 * N + col) = hp;
            *reinterpret_cast<uint32_t*>(Clo + (size_t)r0 * N + col) = lp;
            split_bf16(v10, h0, l0); split_bf16(v11, h1, l1);
            hp = (uint32_t)h0 | ((uint32_t)h1 << 16);
            lp = (uint32_t)l0 | ((uint32_t)l1 << 16);
            *reinterpret_cast<uint32_t*>(Chi + (size_t)r1 * N + col) = hp;
            *reinterpret_cast<uint32_t*>(Clo + (size_t)r1 * N + col) = lp;
        }
    }
}

// ---------------- head GEMM (SIMT, small N), A from split planes ----------
template <int ACT>   // 0 identity, 2 = 4*sigmoid
__global__ __launch_bounds__(256) void sgemm_head(
    const __nv_bfloat16* __restrict__ Ahi, const __nv_bfloat16* __restrict__ Alo,
    const float* __restrict__ W, const float* __restrict__ bias,
    float* __restrict__ C, int M, int N, int K)
{
    __shared__ float As[8][128];
    __shared__ float Ws[8][128];
    const int tid = threadIdx.x;
    const int tx = tid & 15, ty = tid >> 4;
    const int m0 = blockIdx.y * 128, n0 = blockIdx.x * 128;
    const int lrow = tid >> 1, lk = (tid & 1) * 4;
    const size_t arow = (size_t)(m0 + lrow) * K + lk;
    const int wrow = n0 + lrow;
    const float* Wp = W + (size_t)wrow * K + lk;
    const bool wok = (wrow < N);

    float acc[8][8];
#pragma unroll
    for (int i = 0; i < 8; i++)
#pragma unroll
        for (int j = 0; j < 8; j++) acc[i][j] = 0.f;

    for (int k0 = 0; k0 < K; k0 += 8) {
        const __nv_bfloat162* hp = reinterpret_cast<const __nv_bfloat162*>(Ahi + arow + k0);
        const __nv_bfloat162* lp = reinterpret_cast<const __nv_bfloat162*>(Alo + arow + k0);
        __nv_bfloat162 h0 = hp[0], h1 = hp[1], l0 = lp[0], l1 = lp[1];
        float4 wv = wok ? *reinterpret_cast<const float4*>(Wp + k0)
                        : make_float4(0.f, 0.f, 0.f, 0.f);
        As[lk + 0][lrow] = __bfloat162float(h0.x) + __bfloat162float(l0.x);
        As[lk + 1][lrow] = __bfloat162float(h0.y) + __bfloat162float(l0.y);
        As[lk + 2][lrow] = __bfloat162float(h1.x) + __bfloat162float(l1.x);
        As[lk + 3][lrow] = __bfloat162float(h1.y) + __bfloat162float(l1.y);
        Ws[lk + 0][lrow] = wv.x; Ws[lk + 1][lrow] = wv.y;
        Ws[lk + 2][lrow] = wv.z; Ws[lk + 3][lrow] = wv.w;
        __syncthreads();
#pragma unroll
        for (int kk = 0; kk < 8; kk++) {
            float ar[8], wr[8];
            *reinterpret_cast<float4*>(ar)     = *reinterpret_cast<const float4*>(&As[kk][ty * 8]);
            *reinterpret_cast<float4*>(ar + 4) = *reinterpret_cast<const float4*>(&As[kk][ty * 8 + 4]);
            *reinterpret_cast<float4*>(wr)     = *reinterpret_cast<const float4*>(&Ws[kk][tx * 8]);
            *reinterpret_cast<float4*>(wr + 4) = *reinterpret_cast<const float4*>(&Ws[kk][tx * 8 + 4]);
#pragma unroll
            for (int i = 0; i < 8; i++)
#pragma unroll
                for (int j = 0; j < 8; j++)
                    acc[i][j] = fmaf(ar[i], wr[j], acc[i][j]);
        }
        __syncthreads();
    }
#pragma unroll
    for (int i = 0; i < 8; i++) {
        const int row = m0 + ty * 8 + i;
#pragma unroll
        for (int j = 0; j < 8; j++) {
            const int col = n0 + tx * 8 + j;
            if (col < N) {
                float v = acc[i][j] + bias[col];
                if (ACT == 2) v = 4.f / (1.f + expf(-v));
                C[(size_t)row * N + col] = v;
            }
        }
    }
}

// ---------------- fused CBF-QP epilogue ----------------
__global__ void final_kernel(const float* __restrict__ x,
                             const float* __restrict__ mean,
                             const float* __restrict__ stdv,
                             const float* __restrict__ mean_label,
                             const float* __restrict__ std_label,
                             const float* __restrict__ x51,
                             const float* __restrict__ x52,
                             const float* __restrict__ wt,
                             float* __restrict__ out)
{
    int b = blockIdx.x * blockDim.x + threadIdx.x;
    if (b >= BATCH) return;

    float4 xv = reinterpret_cast<const float4*>(x)[b];
    float th1 = xv.x * stdv[0] + mean[0];
    float w1v = xv.y * stdv[1] + mean[1];
    float th2 = xv.z * stdv[2] + mean[2];
    float w2v = xv.w * stdv[3] + mean[3];

    float s1, c1, s2, c2;
    sincosf(th1, &s1, &c1);
    sincosf(th2, &s2, &c2);

    const float Lc = 3.0f;
    float px = Lc * c1 + Lc * c2;
    float py = Lc * s1 + Lc * s2 - 7.0f;
    float vx = -Lc * s1 * w1v - Lc * s2 * w2v;
    float vy =  Lc * c1 * w1v + Lc * c2 * w2v;
    float barrier = px * px + py * py - 16.0f;
    float b_dot = 2.0f * (px * vx + py * vy);
    float Lf2b = 2.0f * vx * vx + 2.0f * vy * vy
               + 2.0f * px * (-Lc * c1 * w1v * w1v - Lc * c2 * w2v * w2v)
               + 2.0f * py * (-Lc * s1 * w1v * w1v - Lc * s2 * w2v * w2v);
    float g1 = 2.0f * px * (-Lc * s1) + 2.0f * py * (Lc * c1);
    float g2 = 2.0f * px * (-Lc * s2) + 2.0f * py * (Lc * c2);
    float Gx = -g1, Gy = -g2;
    float Gdot = g1 * g1 + g2 * g2;

    float wmax = wt[0];
#pragma unroll
    for (int h = 1; h < 10; h++) wmax = fmaxf(wmax, wt[h]);
    float wv[10], wsum = 0.f;
#pragma unroll
    for (int h = 0; h < 10; h++) { wv[h] = expf(wt[h] - wmax); wsum += wv[h]; }
    float winv = 1.f / wsum;

    float alpha = x52[(size_t)b * 11 + 0];
    float ax = 0.f, ay = 0.f;
#pragma unroll
    for (int h = 0; h < 10; h++) {
        float beta = x52[(size_t)b * 11 + 1 + h];
        float ux = -x51[(size_t)b * 20 + 2 * h];
        float uy = -x51[(size_t)b * 20 + 2 * h + 1];
        float hv = Lf2b + (alpha + beta) * b_dot + alpha * beta * barrier;
        float viol = ux * Gx + uy * Gy - hv;
        float lam = fmaxf(viol / Gdot, 0.f);
        float wh = wv[h] * winv;
        ax = fmaf(wh, ux - lam * Gx, ax);
        ay = fmaf(wh, uy - lam * Gy, ay);
    }
    out[(size_t)b * 2 + 0] = (ax - mean_label[0]) / std_label[0];
    out[(size_t)b * 2 + 1] = (ay - mean_label[1]) / std_label[1];
}

// ---------------- kernel_launch ----------------
extern "C" void kernel_launch(void* const* d_in, const int* in_sizes, int n_in,
                              void* d_out, int out_size)
{
    (void)in_sizes; (void)n_in; (void)out_size;

    const float* x          = (const float*)d_in[0];
    const float* mean       = (const float*)d_in[2];
    const float* stdv       = (const float*)d_in[3];
    const float* mean_label = (const float*)d_in[4];
    const float* std_label  = (const float*)d_in[5];
    const float* W1  = (const float*)d_in[6];   const float* b1  = (const float*)d_in[7];
    const float* W2  = (const float*)d_in[8];   const float* b2  = (const float*)d_in[9];
    const float* W31 = (const float*)d_in[10];  const float* b31 = (const float*)d_in[11];
    const float* W32 = (const float*)d_in[12];  const float* b32 = (const float*)d_in[13];
    const float* W41 = (const float*)d_in[14];  const float* b41 = (const float*)d_in[15];
    const float* W42 = (const float*)d_in[16];  const float* b42 = (const float*)d_in[17];
    const float* W51 = (const float*)d_in[18];  const float* b51 = (const float*)d_in[19];
    const float* W52 = (const float*)d_in[20];  const float* b52 = (const float*)d_in[21];
    const float* wt  = (const float*)d_in[22];
    float* out = (float*)d_out;

    static float *bufA = nullptr, *bufB = nullptr, *bufC = nullptr,
                 *x51p = nullptr, *x52p = nullptr;
    static __nv_bfloat16* wsp = nullptr;
    if (!bufA) {
        cudaGetSymbolAddress((void**)&bufA, g_bufA);
        cudaGetSymbolAddress((void**)&bufB, g_bufB);
        cudaGetSymbolAddress((void**)&bufC, g_bufC);
        cudaGetSymbolAddress((void**)&x51p, g_x51);
        cudaGetSymbolAddress((void**)&x52p, g_x52);
        cudaGetSymbolAddress((void**)&wsp, g_wsplit);
        cudaFuncSetAttribute(hgemm_split, cudaFuncAttributeMaxDynamicSharedMemorySize, HG_SMEM);
    }

    // split-plane layout (bf16 element offsets within fp32-sized arenas)
    __nv_bfloat16* A  = (__nv_bfloat16*)bufA;
    __nv_bfloat16* Bb = (__nv_bfloat16*)bufB;
    __nv_bfloat16* Cc = (__nv_bfloat16*)bufC;
    __nv_bfloat16 *h1hi = A,              *h1lo = A + (size_t)33554432;
    __nv_bfloat16 *h2hi = Bb,             *h2lo = Bb + (size_t)33554432;
    __nv_bfloat16 *h31hi = Cc,            *h31lo = Cc + (size_t)16777216;
    __nv_bfloat16 *h32hi = Cc + 33554432, *h32lo = Cc + (size_t)50331648;
    __nv_bfloat16 *h41hi = A,             *h41lo = A + (size_t)16777216;
    __nv_bfloat16 *h42hi = A + 33554432,  *h42lo = A + (size_t)50331648;

    __nv_bfloat16 *W2hi  = wsp,            *W2lo  = wsp + 4194304;
    __nv_bfloat16 *W31hi = wsp + 8388608,  *W31lo = wsp + 10485760;
    __nv_bfloat16 *W32hi = wsp + 12582912, *W32lo = wsp + 14680064;
    __nv_bfloat16 *W41hi = wsp + 16777216, *W41lo = wsp + 17825792;
    __nv_bfloat16 *W42hi = wsp + 18874368, *W42lo = wsp + 19922944;

    dim3 t256(256);

    // weight splits
    wsplit_kernel<<<4096, t256>>>(W2,  W2hi,  W2lo,  1048576);
    wsplit_kernel<<<2048, t256>>>(W31, W31hi, W31lo, 524288);
    wsplit_kernel<<<2048, t256>>>(W32, W32hi, W32lo, 524288);
    wsplit_kernel<<<1024, t256>>>(W41, W41hi, W41lo, 262144);
    wsplit_kernel<<<1024, t256>>>(W42, W42hi, W42lo, 262144);

    // layer 1
    layer1_kernel<<<dim3(8, BATCH), t256>>>(x, W1, b1, h1hi, h1lo);

    // big GEMMs on HMMA tensor pipes
    hgemm_split<<<dim3(16, 128), t256, HG_SMEM>>>(h1hi, h1lo, W2hi, W2lo, b2,
                                                  h2hi, h2lo, 2048, 2048);
    hgemm_split<<<dim3(8, 128), t256, HG_SMEM>>>(h2hi, h2lo, W31hi, W31lo, b31,
                                                 h31hi, h31lo, 1024, 2048);
    hgemm_split<<<dim3(8, 128), t256, HG_SMEM>>>(h2hi, h2lo, W32hi, W32lo, b32,
                                                 h32hi, h32lo, 1024, 2048);
    hgemm_split<<<dim3(8, 128), t256, HG_SMEM>>>(h31hi, h31lo, W41hi, W41lo, b41,
                                                 h41hi, h41lo, 1024, 1024);
    hgemm_split<<<dim3(8, 128), t256, HG_SMEM>>>(h32hi, h32lo, W42hi, W42lo, b42,
                                                 h42hi, h42lo, 1024, 1024);

    // heads
    sgemm_head<0><<<dim3(1, 128), t256>>>(h41hi, h41lo, W51, b51, x51p, BATCH, 20, 1024);
    sgemm_head<2><<<dim3(1, 128), t256>>>(h42hi, h42lo, W52, b52, x52p, BATCH, 11, 1024);

    // fused CBF-QP epilogue
    final_kernel<<<BATCH / 256, 256>>>(x, mean, stdv, mean_label, std_label,
                                       x51p, x52p, wt, out);
}

// round 13
// speedup vs baseline: 11.3737x; 2.3364x over previous
#include <cuda_runtime.h>
#include <cuda_fp16.h>
#include <math.h>
#include <stdint.h>

#define BATCH 16384

// Scratch arenas (__device__ globals). Activations are single fp16 planes.
__device__ float g_bufA[(size_t)BATCH * 2048];
__device__ float g_bufB[(size_t)BATCH * 2048];
__device__ float g_bufC[(size_t)BATCH * 2048];
__device__ float g_x51[(size_t)BATCH * 20];
__device__ float g_x52[(size_t)BATCH * 11];
__device__ __half g_wh[20971520];   // fp16 W2|W31|W32|W41|W42

// ---------------- helpers ----------------
__device__ __forceinline__ uint32_t smem_u32(const void* p) {
    uint32_t a;
    asm("{ .reg .u64 t; cvta.to.shared.u64 t, %1; cvt.u32.u64 %0, t; }" : "=r"(a) : "l"(p));
    return a;
}

#define CP_ASYNC16(smem_addr, gptr) \
    asm volatile("cp.async.cg.shared.global [%0], [%1], 16;" :: "r"(smem_addr), "l"(gptr))
#define CP_COMMIT()  asm volatile("cp.async.commit_group;" ::: "memory")
#define CP_WAIT2()   asm volatile("cp.async.wait_group 2;" ::: "memory")

#define LDSM4(r, a) \
    asm volatile("ldmatrix.sync.aligned.m8n8.x4.shared.b16 {%0,%1,%2,%3}, [%4];" \
        : "=r"((r)[0]), "=r"((r)[1]), "=r"((r)[2]), "=r"((r)[3]) : "r"(a))

#define MMA16816(d, a, b0, b1) \
    asm volatile("mma.sync.aligned.m16n8k16.row.col.f32.f16.f16.f32 " \
        "{%0,%1,%2,%3}, {%4,%5,%6,%7}, {%8,%9}, {%0,%1,%2,%3};" \
        : "+f"((d)[0]), "+f"((d)[1]), "+f"((d)[2]), "+f"((d)[3]) \
        : "r"((a)[0]), "r"((a)[1]), "r"((a)[2]), "r"((a)[3]), \
          "r"(b0), "r"(b1))

// ---------------- weight convert: all 5 weights fp32 -> fp16, one launch ----
__global__ void wconvert_kernel(const float* __restrict__ W2,
                                const float* __restrict__ W31,
                                const float* __restrict__ W32,
                                const float* __restrict__ W41,
                                const float* __restrict__ W42,
                                __half* __restrict__ dst)
{
    int i = blockIdx.x * blockDim.x + threadIdx.x;   // float4 index
    const float* src; size_t si, dbase;
    if      (i < 1048576) { src = W2;  si = i;           dbase = 0; }
    else if (i < 1572864) { src = W31; si = i - 1048576; dbase = 4194304; }
    else if (i < 2097152) { src = W32; si = i - 1572864; dbase = 6291456; }
    else if (i < 2359296) { src = W41; si = i - 2097152; dbase = 8388608; }
    else if (i < 2621440) { src = W42; si = i - 2359296; dbase = 9437184; }
    else return;
    float4 w = reinterpret_cast<const float4*>(src)[si];
    __half2 a = __floats2half2_rn(w.x, w.y);
    __half2 b = __floats2half2_rn(w.z, w.w);
    uint2 v;
    v.x = *reinterpret_cast<uint32_t*>(&a);
    v.y = *reinterpret_cast<uint32_t*>(&b);
    *reinterpret_cast<uint2*>(dst + dbase + si * 4) = v;
}

// ---------------- layer 1 (K=4) -> fp16 plane ----------------
__global__ void layer1_kernel(const float* __restrict__ x,
                              const float* __restrict__ W1,
                              const float* __restrict__ b1,
                              __half* __restrict__ h1)
{
    int n = blockIdx.x * blockDim.x + threadIdx.x;
    int m = blockIdx.y;
    float4 xv = reinterpret_cast<const float4*>(x)[m];
    float4 wv = reinterpret_cast<const float4*>(W1)[n];
    float s = fmaf(xv.x, wv.x, fmaf(xv.y, wv.y, fmaf(xv.z, wv.z, xv.w * wv.w))) + b1[n];
    h1[(size_t)m * 2048 + n] = __float2half_rn(fmaxf(s, 0.f));
}

// ---------------------------------------------------------------------------
// fp16 HMMA GEMM:  C = relu(A[M,K] @ W[N,K]^T + bias)   (single product)
// CTA 128x128, BK=64, 3-stage cp.async pipeline (prefetch distance 2),
// 8 warps (2M x 4N, 64x32 each), ldmatrix.x4 for A and B.
// smem stage: A 16K | W 16K = 32K; 3 stages = 96K.
// ---------------------------------------------------------------------------
#define STAGE_BYTES 32768
#define HG_SMEM (3 * STAGE_BYTES)

__global__ __launch_bounds__(256, 1)
void hgemm_f16(const __half* __restrict__ A,
               const __half* __restrict__ W,
               const float* __restrict__ bias,
               __half* __restrict__ C,
               int N, int K)
{
    extern __shared__ char smem[];
    const uint32_t sbase = smem_u32(smem);
    const int tid  = threadIdx.x;
    const int wid  = tid >> 5;
    const int lane = tid & 31;
    const int warpM = wid & 1;
    const int warpN = wid >> 1;
    const int m0 = blockIdx.y * 128;
    const int n0 = blockIdx.x * 128;

    // cp.async: 4 16B chunks per thread per plane per stage
    const char* gA[4]; const char* gW[4];
    uint32_t soff[4];
#pragma unroll
    for (int j = 0; j < 4; ++j) {
        int ci = tid + (j << 8);             // 0..1023
        int row = ci >> 3, ch = ci & 7;
        gA[j] = (const char*)(A + (size_t)(m0 + row) * K + (ch << 3));
        gW[j] = (const char*)(W + (size_t)(n0 + row) * K + (ch << 3));
        soff[j] = (uint32_t)(row * 128 + ((ch ^ (row & 7)) << 4));
    }

    // ldmatrix lane addressing
    const int laneA = lane & 15;
    const uint32_t aRow  = (uint32_t)(warpM * 64 + laneA) * 128;
    const uint32_t aRm   = (uint32_t)(laneA & 7);
    const uint32_t aHalf = (uint32_t)(lane >> 4);
    const uint32_t bR    = (uint32_t)(lane & 7);
    const uint32_t bHalf = (uint32_t)((lane >> 3) & 1);
    const uint32_t bSub  = (uint32_t)((lane >> 4) & 1);
    const uint32_t bRowB = (uint32_t)(warpN * 32 + bSub * 8 + bR) * 128;

    float acc[4][4][4];
#pragma unroll
    for (int mt = 0; mt < 4; ++mt)
#pragma unroll
        for (int nt = 0; nt < 4; ++nt)
#pragma unroll
            for (int r = 0; r < 4; ++r) acc[mt][nt][r] = 0.f;

    const int nK = K >> 6;

    // preload stages 0,1
#pragma unroll
    for (int s = 0; s < 2; ++s) {
        uint32_t st = sbase + s * STAGE_BYTES;
        const uint32_t gadd = (uint32_t)s * 128;
#pragma unroll
        for (int j = 0; j < 4; ++j) {
            CP_ASYNC16(st + soff[j],         gA[j] + gadd);
            CP_ASYNC16(st + 16384 + soff[j], gW[j] + gadd);
        }
        CP_COMMIT();
    }

    int sidx = 0;                    // kb % 3
    int pidx = 2;                    // (kb+2) % 3
    for (int kb = 0; kb < nK; ++kb) {
        const int pf = kb + 2;
        if (pf < nK) {
            uint32_t st = sbase + pidx * STAGE_BYTES;
            const uint32_t gadd = (uint32_t)pf * 128;
#pragma unroll
            for (int j = 0; j < 4; ++j) {
                CP_ASYNC16(st + soff[j],         gA[j] + gadd);
                CP_ASYNC16(st + 16384 + soff[j], gW[j] + gadd);
            }
        }
        CP_COMMIT();                 // possibly-empty group keeps ordering
        CP_WAIT2();
        __syncthreads();

        const uint32_t st = sbase + sidx * STAGE_BYTES;
#pragma unroll
        for (int ks = 0; ks < 4; ++ks) {
            uint32_t a[4][4], b[2][4];
            const uint32_t aCh = (uint32_t)(ks * 2) + aHalf;
            const uint32_t bCh = (uint32_t)(ks * 2) + bHalf;
#pragma unroll
            for (int mt = 0; mt < 4; ++mt)
                LDSM4(a[mt], st + aRow + (uint32_t)(mt * 2048) + ((aCh ^ aRm) << 4));
#pragma unroll
            for (int p = 0; p < 2; ++p)
                LDSM4(b[p], st + 16384 + bRowB + (uint32_t)(p * 2048) + ((bCh ^ bR) << 4));
#pragma unroll
            for (int mt = 0; mt < 4; ++mt) {
                MMA16816(acc[mt][0], a[mt], b[0][0], b[0][1]);
                MMA16816(acc[mt][1], a[mt], b[0][2], b[0][3]);
                MMA16816(acc[mt][2], a[mt], b[1][0], b[1][1]);
                MMA16816(acc[mt][3], a[mt], b[1][2], b[1][3]);
            }
        }
        sidx = (sidx == 2) ? 0 : sidx + 1;
        pidx = (pidx == 2) ? 0 : pidx + 1;
    }

    // epilogue: bias + relu -> fp16 plane
    const int g = lane >> 2, t = lane & 3;
#pragma unroll
    for (int mt = 0; mt < 4; ++mt) {
        const int r0 = m0 + warpM * 64 + mt * 16 + g;
        const int r1 = r0 + 8;
#pragma unroll
        for (int nt = 0; nt < 4; ++nt) {
            const int col = n0 + warpN * 32 + nt * 8 + 2 * t;
            float2 bs = *reinterpret_cast<const float2*>(&bias[col]);
            __half2 p0 = __floats2half2_rn(fmaxf(acc[mt][nt][0] + bs.x, 0.f),
                                           fmaxf(acc[mt][nt][1] + bs.y, 0.f));
            __half2 p1 = __floats2half2_rn(fmaxf(acc[mt][nt][2] + bs.x, 0.f),
                                           fmaxf(acc[mt][nt][3] + bs.y, 0.f));
            *reinterpret_cast<uint32_t*>(C + (size_t)r0 * N + col) =
                *reinterpret_cast<uint32_t*>(&p0);
            *reinterpret_cast<uint32_t*>(C + (size_t)r1 * N + col) =
                *reinterpret_cast<uint32_t*>(&p1);
        }
    }
}

// ---------------- merged head GEMMs (SIMT), fp16 A ----------------
// blockIdx.x = 0: x51 = h41 @ W51^T + b51          (N=20, identity)
// blockIdx.x = 1: x52 = 4*sigmoid(h42 @ W52^T+b52) (N=11)
__global__ __launch_bounds__(256) void heads_kernel(
    const __half* __restrict__ A1, const __half* __restrict__ A2,
    const float* __restrict__ W51, const float* __restrict__ b51,
    float* __restrict__ x51,
    const float* __restrict__ W52, const float* __restrict__ b52,
    float* __restrict__ x52)
{
    const int head = blockIdx.x;
    const __half* Ah   = head ? A2  : A1;
    const float*  Wp0  = head ? W52 : W51;
    const float*  bp   = head ? b52 : b51;
    float*        Cp   = head ? x52 : x51;
    const int     N    = head ? 11 : 20;
    const int     K    = 1024;

    __shared__ float As[8][128];
    __shared__ float Ws[8][128];
    const int tid = threadIdx.x;
    const int tx = tid & 15, ty = tid >> 4;
    const int m0 = blockIdx.y * 128;
    const int lrow = tid >> 1, lk = (tid & 1) * 4;
    const size_t arow = (size_t)(m0 + lrow) * K + lk;
    const int wrow = lrow;
    const float* Wrp = Wp0 + (size_t)wrow * K + lk;
    const bool wok = (wrow < N);

    float acc[8][8];
#pragma unroll
    for (int i = 0; i < 8; i++)
#pragma unroll
        for (int j = 0; j < 8; j++) acc[i][j] = 0.f;

    for (int k0 = 0; k0 < K; k0 += 8) {
        const __half2* hp = reinterpret_cast<const __half2*>(Ah + arow + k0);
        __half2 h0 = hp[0], h1 = hp[1];
        float4 wv = wok ? *reinterpret_cast<const float4*>(Wrp + k0)
                        : make_float4(0.f, 0.f, 0.f, 0.f);
        As[lk + 0][lrow] = __low2float(h0);  As[lk + 1][lrow] = __high2float(h0);
        As[lk + 2][lrow] = __low2float(h1);  As[lk + 3][lrow] = __high2float(h1);
        Ws[lk + 0][lrow] = wv.x; Ws[lk + 1][lrow] = wv.y;
        Ws[lk + 2][lrow] = wv.z; Ws[lk + 3][lrow] = wv.w;
        __syncthreads();
#pragma unroll
        for (int kk = 0; kk < 8; kk++) {
            float ar[8], wr[8];
            *reinterpret_cast<float4*>(ar)     = *reinterpret_cast<const float4*>(&As[kk][ty * 8]);
            *reinterpret_cast<float4*>(ar + 4) = *reinterpret_cast<const float4*>(&As[kk][ty * 8 + 4]);
            *reinterpret_cast<float4*>(wr)     = *reinterpret_cast<const float4*>(&Ws[kk][tx * 8]);
            *reinterpret_cast<float4*>(wr + 4) = *reinterpret_cast<const float4*>(&Ws[kk][tx * 8 + 4]);
#pragma unroll
            for (int i = 0; i < 8; i++)
#pragma unroll
                for (int j = 0; j < 8; j++)
                    acc[i][j] = fmaf(ar[i], wr[j], acc[i][j]);
        }
        __syncthreads();
    }
#pragma unroll
    for (int i = 0; i < 8; i++) {
        const int row = m0 + ty * 8 + i;
#pragma unroll
        for (int j = 0; j < 8; j++) {
            const int col = tx * 8 + j;
            if (col < N) {
                float v = acc[i][j] + bp[col];
                if (head) v = 4.f / (1.f + expf(-v));
                Cp[(size_t)row * N + col] = v;
            }
        }
    }
}

// ---------------- fused CBF-QP epilogue ----------------
__global__ void final_kernel(const float* __restrict__ x,
                             const float* __restrict__ mean,
                             const float* __restrict__ stdv,
                             const float* __restrict__ mean_label,
                             const float* __restrict__ std_label,
                             const float* __restrict__ x51,
                             const float* __restrict__ x52,
                             const float* __restrict__ wt,
                             float* __restrict__ out)
{
    int b = blockIdx.x * blockDim.x + threadIdx.x;
    if (b >= BATCH) return;

    float4 xv = reinterpret_cast<const float4*>(x)[b];
    float th1 = xv.x * stdv[0] + mean[0];
    float w1v = xv.y * stdv[1] + mean[1];
    float th2 = xv.z * stdv[2] + mean[2];
    float w2v = xv.w * stdv[3] + mean[3];

    float s1, c1, s2, c2;
    sincosf(th1, &s1, &c1);
    sincosf(th2, &s2, &c2);

    const float Lc = 3.0f;
    float px = Lc * c1 + Lc * c2;
    float py = Lc * s1 + Lc * s2 - 7.0f;
    float vx = -Lc * s1 * w1v - Lc * s2 * w2v;
    float vy =  Lc * c1 * w1v + Lc * c2 * w2v;
    float barrier = px * px + py * py - 16.0f;
    float b_dot = 2.0f * (px * vx + py * vy);
    float Lf2b = 2.0f * vx * vx + 2.0f * vy * vy
               + 2.0f * px * (-Lc * c1 * w1v * w1v - Lc * c2 * w2v * w2v)
               + 2.0f * py * (-Lc * s1 * w1v * w1v - Lc * s2 * w2v * w2v);
    float g1 = 2.0f * px * (-Lc * s1) + 2.0f * py * (Lc * c1);
    float g2 = 2.0f * px * (-Lc * s2) + 2.0f * py * (Lc * c2);
    float Gx = -g1, Gy = -g2;
    float Gdot = g1 * g1 + g2 * g2;

    float wmax = wt[0];
#pragma unroll
    for (int h = 1; h < 10; h++) wmax = fmaxf(wmax, wt[h]);
    float wv[10], wsum = 0.f;
#pragma unroll
    for (int h = 0; h < 10; h++) { wv[h] = expf(wt[h] - wmax); wsum += wv[h]; }
    float winv = 1.f / wsum;

    float alpha = x52[(size_t)b * 11 + 0];
    float ax = 0.f, ay = 0.f;
#pragma unroll
    for (int h = 0; h < 10; h++) {
        float beta = x52[(size_t)b * 11 + 1 + h];
        float ux = -x51[(size_t)b * 20 + 2 * h];
        float uy = -x51[(size_t)b * 20 + 2 * h + 1];
        float hv = Lf2b + (alpha + beta) * b_dot + alpha * beta * barrier;
        float viol = ux * Gx + uy * Gy - hv;
        float lam = fmaxf(viol / Gdot, 0.f);
        float wh = wv[h] * winv;
        ax = fmaf(wh, ux - lam * Gx, ax);
        ay = fmaf(wh, uy - lam * Gy, ay);
    }
    out[(size_t)b * 2 + 0] = (ax - mean_label[0]) / std_label[0];
    out[(size_t)b * 2 + 1] = (ay - mean_label[1]) / std_label[1];
}

// ---------------- kernel_launch ----------------
extern "C" void kernel_launch(void* const* d_in, const int* in_sizes, int n_in,
                              void* d_out, int out_size)
{
    (void)in_sizes; (void)n_in; (void)out_size;

    const float* x          = (const float*)d_in[0];
    const float* mean       = (const float*)d_in[2];
    const float* stdv       = (const float*)d_in[3];
    const float* mean_label = (const float*)d_in[4];
    const float* std_label  = (const float*)d_in[5];
    const float* W1  = (const float*)d_in[6];   const float* b1  = (const float*)d_in[7];
    const float* W2  = (const float*)d_in[8];   const float* b2  = (const float*)d_in[9];
    const float* W31 = (const float*)d_in[10];  const float* b31 = (const float*)d_in[11];
    const float* W32 = (const float*)d_in[12];  const float* b32 = (const float*)d_in[13];
    const float* W41 = (const float*)d_in[14];  const float* b41 = (const float*)d_in[15];
    const float* W42 = (const float*)d_in[16];  const float* b42 = (const float*)d_in[17];
    const float* W51 = (const float*)d_in[18];  const float* b51 = (const float*)d_in[19];
    const float* W52 = (const float*)d_in[20];  const float* b52 = (const float*)d_in[21];
    const float* wt  = (const float*)d_in[22];
    float* out = (float*)d_out;

    static float *bufA = nullptr, *bufB = nullptr, *bufC = nullptr,
                 *x51p = nullptr, *x52p = nullptr;
    static __half* whp = nullptr;
    if (!bufA) {
        cudaGetSymbolAddress((void**)&bufA, g_bufA);
        cudaGetSymbolAddress((void**)&bufB, g_bufB);
        cudaGetSymbolAddress((void**)&bufC, g_bufC);
        cudaGetSymbolAddress((void**)&x51p, g_x51);
        cudaGetSymbolAddress((void**)&x52p, g_x52);
        cudaGetSymbolAddress((void**)&whp, g_wh);
        cudaFuncSetAttribute(hgemm_f16, cudaFuncAttributeMaxDynamicSharedMemorySize, HG_SMEM);
    }

    // fp16 activation planes inside the fp32 arenas
    __half* h1  = (__half*)bufA;
    __half* h2  = (__half*)bufB;
    __half* h31 = (__half*)bufC;
    __half* h32 = (__half*)bufC + (size_t)16777216;
    __half* h41 = (__half*)bufA;                      // bufA free after GEMM2
    __half* h42 = (__half*)bufA + (size_t)16777216;

    __half* W2h  = whp;
    __half* W31h = whp + 4194304;
    __half* W32h = whp + 6291456;
    __half* W41h = whp + 8388608;
    __half* W42h = whp + 9437184;

    dim3 t256(256);

    // all weight conversions in one launch
    wconvert_kernel<<<10240, t256>>>(W2, W31, W32, W41, W42, whp);

    // layer 1
    layer1_kernel<<<dim3(8, BATCH), t256>>>(x, W1, b1, h1);

    // big GEMMs (single-product fp16 HMMA)
    hgemm_f16<<<dim3(16, 128), t256, HG_SMEM>>>(h1,  W2h,  b2,  h2,  2048, 2048);
    hgemm_f16<<<dim3(8, 128),  t256, HG_SMEM>>>(h2,  W31h, b31, h31, 1024, 2048);
    hgemm_f16<<<dim3(8, 128),  t256, HG_SMEM>>>(h2,  W32h, b32, h32, 1024, 2048);
    hgemm_f16<<<dim3(8, 128),  t256, HG_SMEM>>>(h31, W41h, b41, h41, 1024, 1024);
    hgemm_f16<<<dim3(8, 128),  t256, HG_SMEM>>>(h32, W42h, b42, h42, 1024, 1024);

    // both heads in one launch
    heads_kernel<<<dim3(2, 128), t256>>>(h41, h42, W51, b51, x51p, W52, b52, x52p);

    // fused CBF-QP epilogue
    final_kernel<<<BATCH / 256, 256>>>(x, mean, stdv, mean_label, std_label,
                                       x51p, x52p, wt, out);
}